// round 2
// baseline (speedup 1.0000x reference)
#include <cuda_runtime.h>

// SpringMass: B=4096 independent 2-state linear ODEs, T=4096 RK4 steps each.
// s=(xdot,x); one RK4 step is affine: s' = A(k)*s + F*g(k), with A,g entries
// polynomials in k (deg<=2), coefficients depending only on C,dt.
// => parallel scan over time: per-chunk compose (pass1), block scan (pass2),
// replay with outputs (pass3).
//
// R2 change: register-pressure fix. R1 compiled to 255 regs (ceiling) ->
// occ 11.6%, issue 26% (latency-bound). Force 64 regs via launch_bounds
// (8 CTAs/SM = 32 warps/SM) and cap unrolls to 4 steps to avoid load
// front-batching into the smaller register file.

#define T_LEN  4096
#define NTHR   128
#define CHUNK  (T_LEN / NTHR)   // 32

namespace sm_consts {
constexpr double Cd = 0.1, hd = 0.005, dd = 0.01, wd = dd / 6.0;
// stage 2
constexpr double P2   = 1.0 - hd * Cd;
constexpr double A2c  = -Cd * P2;
constexpr double A2k  = -hd;
constexpr double B2k  = Cd * hd - 1.0;
constexpr double G2   = 1.0 - Cd * hd;
// stage 3 args
constexpr double Va3c = 1.0 + hd * A2c;
constexpr double Va3k = hd * A2k;
constexpr double Vb3k = hd * B2k;
constexpr double Vg3  = hd * G2;
constexpr double Xa3v = hd * P2;
constexpr double Xa3xk = -hd * hd;
constexpr double Xa3f  = hd * hd;
// stage 3
constexpr double A3c  = -Cd * Va3c;
constexpr double A3k  = -Cd * Va3k - Xa3v;
constexpr double B3k  = -Cd * Vb3k - 1.0;
constexpr double B3k2 = -Xa3xk;
constexpr double G3c  = 1.0 - Cd * Vg3;
constexpr double G3k  = -Xa3f;
// stage 4 args
constexpr double Va4c = 1.0 + dd * A3c;
constexpr double Va4k = dd * A3k;
constexpr double Vb4k  = dd * B3k;
constexpr double Vb4k2 = dd * B3k2;
constexpr double Vg4c  = dd * G3c;
constexpr double Vg4k  = dd * G3k;
constexpr double Xa4vc = dd * Va3c, Xa4vk = dd * Va3k;
constexpr double Xa4xk = dd * Vb3k;
constexpr double Xa4f  = dd * Vg3;
// stage 4
constexpr double A4c  = -Cd * Va4c;
constexpr double A4k  = -Cd * Va4k - Xa4vc;
constexpr double A4k2 = -Xa4vk;
constexpr double B4k  = -Cd * Vb4k - 1.0;
constexpr double B4k2 = -Cd * Vb4k2 - Xa4xk;
constexpr double G4c  = 1.0 - Cd * Vg4c;
constexpr double G4k  = -Cd * Vg4k - Xa4f;

// Final per-step map coefficients (polynomials in k):
constexpr float K110 = (float)(1.0 + wd * (-Cd + 2*A2c + 2*A3c + A4c));
constexpr float K111 = (float)(wd * (2*A2k + 2*A3k + A4k));
constexpr float K112 = (float)(wd * A4k2);
constexpr float K121 = (float)(wd * (-1.0 + 2*B2k + 2*B3k + B4k));
constexpr float K122 = (float)(wd * (2*B3k2 + B4k2));
constexpr float KG10 = (float)(wd * (1.0 + 2*G2 + 2*G3c + G4c));
constexpr float KG11 = (float)(wd * (2*G3k + G4k));
constexpr float K210 = (float)(wd * (1.0 + 2*P2 + 2*Va3c + Va4c));
constexpr float K211 = (float)(wd * (2*Va3k + Va4k));
constexpr float K221 = (float)(wd * (-2.0*hd + 2*Vb3k + Vb4k));
constexpr float K222 = (float)(wd * Vb4k2);
constexpr float KG20 = (float)(wd * (2.0*hd + 2*Vg3 + Vg4c));
constexpr float KG21 = (float)(wd * Vg4k);
constexpr float CF   = 0.1f;
}  // namespace sm_consts

struct Aff { float a11, a12, a21, a22, b1, b2; };

// result = newer ∘ older  (older applied first in time)
__device__ __forceinline__ Aff compose(const Aff& n, const Aff& o) {
    Aff r;
    r.a11 = fmaf(n.a11, o.a11, n.a12 * o.a21);
    r.a12 = fmaf(n.a11, o.a12, n.a12 * o.a22);
    r.a21 = fmaf(n.a21, o.a11, n.a22 * o.a21);
    r.a22 = fmaf(n.a21, o.a12, n.a22 * o.a22);
    r.b1  = fmaf(n.a11, o.b1, fmaf(n.a12, o.b2, n.b1));
    r.b2  = fmaf(n.a21, o.b1, fmaf(n.a22, o.b2, n.b2));
    return r;
}

__device__ __forceinline__ Aff step_map(float k, float F) {
    using namespace sm_consts;
    Aff s;
    s.a11 = fmaf(fmaf(K112, k, K111), k, K110);
    s.a12 = k * fmaf(K122, k, K121);
    s.a21 = fmaf(K211, k, K210);
    s.a22 = fmaf(fmaf(K222, k, K221), k, 1.0f);
    s.b1 = F * fmaf(KG11, k, KG10);
    s.b2 = F * fmaf(KG21, k, KG20);
    return s;
}

// advance state, return xddot for this step (computed from NEW state)
__device__ __forceinline__ float step_state(float k, float F, float& v, float& x) {
    using namespace sm_consts;
    float A11 = fmaf(fmaf(K112, k, K111), k, K110);
    float A12 = k * fmaf(K122, k, K121);
    float A21 = fmaf(K211, k, K210);
    float A22 = fmaf(fmaf(K222, k, K221), k, 1.0f);
    float g1  = fmaf(KG11, k, KG10);
    float g2  = fmaf(KG21, k, KG20);
    float vn = fmaf(A11, v, fmaf(A12, x, F * g1));
    float xn = fmaf(A21, v, fmaf(A22, x, F * g2));
    v = vn; x = xn;
    return fmaf(-k, xn, fmaf(-CF, vn, F));   // (-C*v' - k*x' + F)/M, M=1
}

__device__ __forceinline__ Aff shfl_up_aff(const Aff& m, int off) {
    Aff r;
    r.a11 = __shfl_up_sync(0xffffffffu, m.a11, off);
    r.a12 = __shfl_up_sync(0xffffffffu, m.a12, off);
    r.a21 = __shfl_up_sync(0xffffffffu, m.a21, off);
    r.a22 = __shfl_up_sync(0xffffffffu, m.a22, off);
    r.b1  = __shfl_up_sync(0xffffffffu, m.b1,  off);
    r.b2  = __shfl_up_sync(0xffffffffu, m.b2,  off);
    return r;
}

__global__ void __launch_bounds__(NTHR, 8)
spring_scan_kernel(const float* __restrict__ in,
                   const float* __restrict__ vinit,
                   const float* __restrict__ xinit,
                   float* __restrict__ out) {
    const int b = blockIdx.x;
    const int l = threadIdx.x;
    const int lane = l & 31;
    const int w = l >> 5;

    const float* base = in + ((long)b * T_LEN + (long)l * CHUNK) * 2;

    // ---- Pass 1: compose this thread's 32-step chunk map ----
    Aff M = {1.f, 0.f, 0.f, 1.f, 0.f, 0.f};
#pragma unroll 4
    for (int s = 0; s < CHUNK; s += 2) {
        float4 d = *reinterpret_cast<const float4*>(base + s * 2);
        M = compose(step_map(d.x, d.y), M);
        M = compose(step_map(d.z, d.w), M);
    }

    // ---- Pass 2: block-wide scan of affine maps ----
#pragma unroll
    for (int off = 1; off < 32; off <<= 1) {
        Aff o = shfl_up_aff(M, off);
        if (lane >= off) M = compose(M, o);
    }

    __shared__ Aff wsum[NTHR / 32];
    if (lane == 31) wsum[w] = M;
    __syncthreads();

    // prefix over preceding warps
    Aff pre = {1.f, 0.f, 0.f, 1.f, 0.f, 0.f};
    for (int j = 0; j < w; j++) pre = compose(wsum[j], pre);

    // in-warp exclusive value
    Aff eo = shfl_up_aff(M, 1);
    Aff excl;
    if (lane == 0) { excl.a11 = 1.f; excl.a12 = 0.f; excl.a21 = 0.f;
                     excl.a22 = 1.f; excl.b1 = 0.f;  excl.b2 = 0.f; }
    else           { excl = eo; }

    Aff tot = compose(excl, pre);   // exclusive prefix of all earlier chunks

    // state entering this chunk
    float vi = vinit[b], xi = xinit[b];
    float v = fmaf(tot.a11, vi, fmaf(tot.a12, xi, tot.b1));
    float x = fmaf(tot.a21, vi, fmaf(tot.a22, xi, tot.b2));

    // ---- Pass 3: replay chunk, emit xddot ----
    float* obase = out + (long)b * T_LEN + (long)l * CHUNK;
#pragma unroll 2
    for (int s = 0; s < CHUNK; s += 4) {
        float4 d0 = *reinterpret_cast<const float4*>(base + s * 2);
        float4 d1 = *reinterpret_cast<const float4*>(base + s * 2 + 4);
        float4 o;
        o.x = step_state(d0.x, d0.y, v, x);
        o.y = step_state(d0.z, d0.w, v, x);
        o.z = step_state(d1.x, d1.y, v, x);
        o.w = step_state(d1.z, d1.w, v, x);
        *reinterpret_cast<float4*>(obase + s) = o;
    }
}

extern "C" void kernel_launch(void* const* d_in, const int* in_sizes, int n_in,
                              void* d_out, int out_size) {
    const float* in = (const float*)d_in[0];       // (B, T, 2) float32
    const float* vi = (const float*)d_in[1];       // (B, 1)
    const float* xi = (const float*)d_in[2];       // (B, 1)
    float* out = (float*)d_out;                    // (B, T, 1) float32
    const int B = in_sizes[1];                     // 4096
    spring_scan_kernel<<<B, NTHR>>>(in, vi, xi, out);
}

// round 3
// speedup vs baseline: 1.4779x; 1.4779x over previous
#include <cuda_runtime.h>

// SpringMass: B=4096 independent 2-state linear ODEs, T=4096 RK4 steps each.
// Affine scan over time (pass1 compose / pass2 block scan / pass3 replay).
//
// R3 change: kill L1 wavefront amplification. Chunk-per-thread global
// accesses touched 32 lines per warp LDG/STG (L1 at 89%). Now: coalesced
// global <-> swizzled smem staging; both compute passes read smem; output
// staged in-place in the same tile and written coalesced. Global input is
// read exactly once.

#define T_LEN  4096
#define NTHR   128
#define CHUNK  (T_LEN / NTHR)     // 32 steps / thread
#define F4C    16                 // input float4 per chunk
#define O4C    8                  // output float4 per chunk

namespace sm_consts {
constexpr double Cd = 0.1, hd = 0.005, dd = 0.01, wd = dd / 6.0;
constexpr double P2   = 1.0 - hd * Cd;
constexpr double A2c  = -Cd * P2;
constexpr double A2k  = -hd;
constexpr double B2k  = Cd * hd - 1.0;
constexpr double G2   = 1.0 - Cd * hd;
constexpr double Va3c = 1.0 + hd * A2c;
constexpr double Va3k = hd * A2k;
constexpr double Vb3k = hd * B2k;
constexpr double Vg3  = hd * G2;
constexpr double Xa3v = hd * P2;
constexpr double Xa3xk = -hd * hd;
constexpr double Xa3f  = hd * hd;
constexpr double A3c  = -Cd * Va3c;
constexpr double A3k  = -Cd * Va3k - Xa3v;
constexpr double B3k  = -Cd * Vb3k - 1.0;
constexpr double B3k2 = -Xa3xk;
constexpr double G3c  = 1.0 - Cd * Vg3;
constexpr double G3k  = -Xa3f;
constexpr double Va4c = 1.0 + dd * A3c;
constexpr double Va4k = dd * A3k;
constexpr double Vb4k  = dd * B3k;
constexpr double Vb4k2 = dd * B3k2;
constexpr double Vg4c  = dd * G3c;
constexpr double Vg4k  = dd * G3k;
constexpr double Xa4vc = dd * Va3c, Xa4vk = dd * Va3k;
constexpr double Xa4xk = dd * Vb3k;
constexpr double Xa4f  = dd * Vg3;
constexpr double A4c  = -Cd * Va4c;
constexpr double A4k  = -Cd * Va4k - Xa4vc;
constexpr double A4k2 = -Xa4vk;
constexpr double B4k  = -Cd * Vb4k - 1.0;
constexpr double B4k2 = -Cd * Vb4k2 - Xa4xk;
constexpr double G4c  = 1.0 - Cd * Vg4c;
constexpr double G4k  = -Cd * Vg4k - Xa4f;

constexpr float K110 = (float)(1.0 + wd * (-Cd + 2*A2c + 2*A3c + A4c));
constexpr float K111 = (float)(wd * (2*A2k + 2*A3k + A4k));
constexpr float K112 = (float)(wd * A4k2);
constexpr float K121 = (float)(wd * (-1.0 + 2*B2k + 2*B3k + B4k));
constexpr float K122 = (float)(wd * (2*B3k2 + B4k2));
constexpr float KG10 = (float)(wd * (1.0 + 2*G2 + 2*G3c + G4c));
constexpr float KG11 = (float)(wd * (2*G3k + G4k));
constexpr float K210 = (float)(wd * (1.0 + 2*P2 + 2*Va3c + Va4c));
constexpr float K211 = (float)(wd * (2*Va3k + Va4k));
constexpr float K221 = (float)(wd * (-2.0*hd + 2*Vb3k + Vb4k));
constexpr float K222 = (float)(wd * Vb4k2);
constexpr float KG20 = (float)(wd * (2.0*hd + 2*Vg3 + Vg4c));
constexpr float KG21 = (float)(wd * Vg4k);
constexpr float CF   = 0.1f;
}  // namespace sm_consts

struct Aff { float a11, a12, a21, a22, b1, b2; };

__device__ __forceinline__ Aff compose(const Aff& n, const Aff& o) {
    Aff r;
    r.a11 = fmaf(n.a11, o.a11, n.a12 * o.a21);
    r.a12 = fmaf(n.a11, o.a12, n.a12 * o.a22);
    r.a21 = fmaf(n.a21, o.a11, n.a22 * o.a21);
    r.a22 = fmaf(n.a21, o.a12, n.a22 * o.a22);
    r.b1  = fmaf(n.a11, o.b1, fmaf(n.a12, o.b2, n.b1));
    r.b2  = fmaf(n.a21, o.b1, fmaf(n.a22, o.b2, n.b2));
    return r;
}

__device__ __forceinline__ Aff step_map(float k, float F) {
    using namespace sm_consts;
    Aff s;
    s.a11 = fmaf(fmaf(K112, k, K111), k, K110);
    s.a12 = k * fmaf(K122, k, K121);
    s.a21 = fmaf(K211, k, K210);
    s.a22 = fmaf(fmaf(K222, k, K221), k, 1.0f);
    s.b1 = F * fmaf(KG11, k, KG10);
    s.b2 = F * fmaf(KG21, k, KG20);
    return s;
}

__device__ __forceinline__ float step_state(float k, float F, float& v, float& x) {
    using namespace sm_consts;
    float A11 = fmaf(fmaf(K112, k, K111), k, K110);
    float A12 = k * fmaf(K122, k, K121);
    float A21 = fmaf(K211, k, K210);
    float A22 = fmaf(fmaf(K222, k, K221), k, 1.0f);
    float g1  = fmaf(KG11, k, KG10);
    float g2  = fmaf(KG21, k, KG20);
    float vn = fmaf(A11, v, fmaf(A12, x, F * g1));
    float xn = fmaf(A21, v, fmaf(A22, x, F * g2));
    v = vn; x = xn;
    return fmaf(-k, xn, fmaf(-CF, vn, F));
}

__device__ __forceinline__ Aff shfl_up_aff(const Aff& m, int off) {
    Aff r;
    r.a11 = __shfl_up_sync(0xffffffffu, m.a11, off);
    r.a12 = __shfl_up_sync(0xffffffffu, m.a12, off);
    r.a21 = __shfl_up_sync(0xffffffffu, m.a21, off);
    r.a22 = __shfl_up_sync(0xffffffffu, m.a22, off);
    r.b1  = __shfl_up_sync(0xffffffffu, m.b1,  off);
    r.b2  = __shfl_up_sync(0xffffffffu, m.b2,  off);
    return r;
}

// smem slot for (chunk c, float4 offset o): XOR swizzle keeps per-thread
// chunk reads and coalesced stores conflict-free per 8-lane phase.
__device__ __forceinline__ int slot(int c, int o) {
    return c * F4C + (o ^ (c & 7));
}

__global__ void __launch_bounds__(NTHR, 7)
spring_scan_kernel(const float* __restrict__ in,
                   const float* __restrict__ vinit,
                   const float* __restrict__ xinit,
                   float* __restrict__ out) {
    __shared__ float4 buf[NTHR * F4C];     // 32 KB tile (input, then output in place)
    __shared__ Aff wsum[NTHR / 32];

    const int b = blockIdx.x;
    const int l = threadIdx.x;
    const int lane = l & 31;
    const int w = l >> 5;

    // ---- Stage: coalesced global -> swizzled smem (read input ONCE) ----
    const float4* gin = reinterpret_cast<const float4*>(in + (long)b * T_LEN * 2);
#pragma unroll
    for (int r = 0; r < 16; r++) {
        int idx = r * NTHR + l;            // float4 index within row, coalesced
        float4 d = gin[idx];
        buf[slot(idx >> 4, idx & 15)] = d;
    }
    __syncthreads();

    // ---- Pass 1: compose this thread's 32-step chunk map (from smem) ----
    Aff M = {1.f, 0.f, 0.f, 1.f, 0.f, 0.f};
#pragma unroll 4
    for (int o = 0; o < F4C; o++) {
        float4 d = buf[slot(l, o)];
        M = compose(step_map(d.x, d.y), M);
        M = compose(step_map(d.z, d.w), M);
    }

    // ---- Pass 2: block-wide scan of affine maps ----
#pragma unroll
    for (int off = 1; off < 32; off <<= 1) {
        Aff o = shfl_up_aff(M, off);
        if (lane >= off) M = compose(M, o);
    }

    if (lane == 31) wsum[w] = M;
    __syncthreads();

    Aff pre = {1.f, 0.f, 0.f, 1.f, 0.f, 0.f};
    for (int j = 0; j < w; j++) pre = compose(wsum[j], pre);

    Aff eo = shfl_up_aff(M, 1);
    Aff excl;
    if (lane == 0) { excl.a11 = 1.f; excl.a12 = 0.f; excl.a21 = 0.f;
                     excl.a22 = 1.f; excl.b1 = 0.f;  excl.b2 = 0.f; }
    else           { excl = eo; }

    Aff tot = compose(excl, pre);

    float vi = vinit[b], xi = xinit[b];
    float v = fmaf(tot.a11, vi, fmaf(tot.a12, xi, tot.b1));
    float x = fmaf(tot.a21, vi, fmaf(tot.a22, xi, tot.b2));

    __syncthreads();   // wsum read done; now safe to start overwriting buf

    // ---- Pass 3: replay chunk from smem, write xddot back IN PLACE ----
    // Output float4 j (steps 4j..4j+3) consumes input float4s 2j, 2j+1 and
    // overwrites the slot of input float4 j (already consumed: j <= 2j).
#pragma unroll 4
    for (int j = 0; j < O4C; j++) {
        float4 d0 = buf[slot(l, 2 * j)];
        float4 d1 = buf[slot(l, 2 * j + 1)];
        float4 o4;
        o4.x = step_state(d0.x, d0.y, v, x);
        o4.y = step_state(d0.z, d0.w, v, x);
        o4.z = step_state(d1.x, d1.y, v, x);
        o4.w = step_state(d1.z, d1.w, v, x);
        buf[slot(l, j)] = o4;
    }
    __syncthreads();

    // ---- Drain: swizzled smem -> coalesced global store ----
    float4* gout = reinterpret_cast<float4*>(out + (long)b * T_LEN);
#pragma unroll
    for (int r = 0; r < 8; r++) {
        int idx = r * NTHR + l;            // output float4 index, coalesced
        gout[idx] = buf[slot(idx >> 3, idx & 7)];
    }
}

extern "C" void kernel_launch(void* const* d_in, const int* in_sizes, int n_in,
                              void* d_out, int out_size) {
    const float* in = (const float*)d_in[0];       // (B, T, 2) float32
    const float* vi = (const float*)d_in[1];       // (B, 1)
    const float* xi = (const float*)d_in[2];       // (B, 1)
    float* out = (float*)d_out;                    // (B, T, 1) float32
    const int B = in_sizes[1];                     // 4096
    spring_scan_kernel<<<B, NTHR>>>(in, vi, xi, out);
}

// round 4
// speedup vs baseline: 1.6314x; 1.1039x over previous
#include <cuda_runtime.h>

// SpringMass: B=4096 independent 2-state linear ODEs, T=4096 RK4 steps each.
// Affine scan over time (pass1 compose / pass2 block scan / pass3 replay).
//
// R4 change: residency. 33KB tile capped SM at 6 CTAs (occ 35%, issue 53%).
// Now the row is processed in two 2048-step halves with a carried (v,x)
// state: 16KB tile + launch_bounds(128,10) -> 10 CTAs = 40 warps/SM.

#define T_LEN  4096
#define NTHR   128
#define HALF   (T_LEN / 2)        // 2048 steps per phase
#define CHUNK  (HALF / NTHR)      // 16 steps / thread / phase
#define F4C    8                  // input float4 per chunk
#define O4C    4                  // output float4 per chunk

namespace sm_consts {
constexpr double Cd = 0.1, hd = 0.005, dd = 0.01, wd = dd / 6.0;
constexpr double P2   = 1.0 - hd * Cd;
constexpr double A2c  = -Cd * P2;
constexpr double A2k  = -hd;
constexpr double B2k  = Cd * hd - 1.0;
constexpr double G2   = 1.0 - Cd * hd;
constexpr double Va3c = 1.0 + hd * A2c;
constexpr double Va3k = hd * A2k;
constexpr double Vb3k = hd * B2k;
constexpr double Vg3  = hd * G2;
constexpr double Xa3v = hd * P2;
constexpr double Xa3xk = -hd * hd;
constexpr double Xa3f  = hd * hd;
constexpr double A3c  = -Cd * Va3c;
constexpr double A3k  = -Cd * Va3k - Xa3v;
constexpr double B3k  = -Cd * Vb3k - 1.0;
constexpr double B3k2 = -Xa3xk;
constexpr double G3c  = 1.0 - Cd * Vg3;
constexpr double G3k  = -Xa3f;
constexpr double Va4c = 1.0 + dd * A3c;
constexpr double Va4k = dd * A3k;
constexpr double Vb4k  = dd * B3k;
constexpr double Vb4k2 = dd * B3k2;
constexpr double Vg4c  = dd * G3c;
constexpr double Vg4k  = dd * G3k;
constexpr double Xa4vc = dd * Va3c, Xa4vk = dd * Va3k;
constexpr double Xa4xk = dd * Vb3k;
constexpr double Xa4f  = dd * Vg3;
constexpr double A4c  = -Cd * Va4c;
constexpr double A4k  = -Cd * Va4k - Xa4vc;
constexpr double A4k2 = -Xa4vk;
constexpr double B4k  = -Cd * Vb4k - 1.0;
constexpr double B4k2 = -Cd * Vb4k2 - Xa4xk;
constexpr double G4c  = 1.0 - Cd * Vg4c;
constexpr double G4k  = -Cd * Vg4k - Xa4f;

constexpr float K110 = (float)(1.0 + wd * (-Cd + 2*A2c + 2*A3c + A4c));
constexpr float K111 = (float)(wd * (2*A2k + 2*A3k + A4k));
constexpr float K112 = (float)(wd * A4k2);
constexpr float K121 = (float)(wd * (-1.0 + 2*B2k + 2*B3k + B4k));
constexpr float K122 = (float)(wd * (2*B3k2 + B4k2));
constexpr float KG10 = (float)(wd * (1.0 + 2*G2 + 2*G3c + G4c));
constexpr float KG11 = (float)(wd * (2*G3k + G4k));
constexpr float K210 = (float)(wd * (1.0 + 2*P2 + 2*Va3c + Va4c));
constexpr float K211 = (float)(wd * (2*Va3k + Va4k));
constexpr float K221 = (float)(wd * (-2.0*hd + 2*Vb3k + Vb4k));
constexpr float K222 = (float)(wd * Vb4k2);
constexpr float KG20 = (float)(wd * (2.0*hd + 2*Vg3 + Vg4c));
constexpr float KG21 = (float)(wd * Vg4k);
constexpr float CF   = 0.1f;
}  // namespace sm_consts

struct Aff { float a11, a12, a21, a22, b1, b2; };

__device__ __forceinline__ Aff compose(const Aff& n, const Aff& o) {
    Aff r;
    r.a11 = fmaf(n.a11, o.a11, n.a12 * o.a21);
    r.a12 = fmaf(n.a11, o.a12, n.a12 * o.a22);
    r.a21 = fmaf(n.a21, o.a11, n.a22 * o.a21);
    r.a22 = fmaf(n.a21, o.a12, n.a22 * o.a22);
    r.b1  = fmaf(n.a11, o.b1, fmaf(n.a12, o.b2, n.b1));
    r.b2  = fmaf(n.a21, o.b1, fmaf(n.a22, o.b2, n.b2));
    return r;
}

__device__ __forceinline__ Aff step_map(float k, float F) {
    using namespace sm_consts;
    Aff s;
    s.a11 = fmaf(fmaf(K112, k, K111), k, K110);
    s.a12 = k * fmaf(K122, k, K121);
    s.a21 = fmaf(K211, k, K210);
    s.a22 = fmaf(fmaf(K222, k, K221), k, 1.0f);
    s.b1 = F * fmaf(KG11, k, KG10);
    s.b2 = F * fmaf(KG21, k, KG20);
    return s;
}

__device__ __forceinline__ float step_state(float k, float F, float& v, float& x) {
    using namespace sm_consts;
    float A11 = fmaf(fmaf(K112, k, K111), k, K110);
    float A12 = k * fmaf(K122, k, K121);
    float A21 = fmaf(K211, k, K210);
    float A22 = fmaf(fmaf(K222, k, K221), k, 1.0f);
    float g1  = fmaf(KG11, k, KG10);
    float g2  = fmaf(KG21, k, KG20);
    float vn = fmaf(A11, v, fmaf(A12, x, F * g1));
    float xn = fmaf(A21, v, fmaf(A22, x, F * g2));
    v = vn; x = xn;
    return fmaf(-k, xn, fmaf(-CF, vn, F));
}

__device__ __forceinline__ Aff shfl_up_aff(const Aff& m, int off) {
    Aff r;
    r.a11 = __shfl_up_sync(0xffffffffu, m.a11, off);
    r.a12 = __shfl_up_sync(0xffffffffu, m.a12, off);
    r.a21 = __shfl_up_sync(0xffffffffu, m.a21, off);
    r.a22 = __shfl_up_sync(0xffffffffu, m.a22, off);
    r.b1  = __shfl_up_sync(0xffffffffu, m.b1,  off);
    r.b2  = __shfl_up_sync(0xffffffffu, m.b2,  off);
    return r;
}

// smem slot for (chunk c, float4 offset o): XOR swizzle keeps per-chunk
// strided reads conflict-free per 8-lane LDS.128 phase.
__device__ __forceinline__ int slot(int c, int o) {
    return c * F4C + (o ^ (c & 7));
}

__global__ void __launch_bounds__(NTHR, 10)
spring_scan_kernel(const float* __restrict__ in,
                   const float* __restrict__ vinit,
                   const float* __restrict__ xinit,
                   float* __restrict__ out) {
    __shared__ float4 buf[NTHR * F4C];     // 16 KB half-row tile
    __shared__ Aff wsum[NTHR / 32];

    const int b = blockIdx.x;
    const int l = threadIdx.x;
    const int lane = l & 31;
    const int w = l >> 5;

    const float4* gin  = reinterpret_cast<const float4*>(in + (long)b * T_LEN * 2);
    float4*       gout = reinterpret_cast<float4*>(out + (long)b * T_LEN);

    float vh = vinit[b], xh = xinit[b];    // state entering current half

#pragma unroll 1
    for (int half = 0; half < 2; half++) {
        const float4* gin_h  = gin  + half * (HALF / 2);   // 1024 float4 per half
        float4*       gout_h = gout + half * (HALF / 4);   // 512 float4 per half

        // ---- Stage: coalesced global -> swizzled smem ----
#pragma unroll
        for (int r = 0; r < F4C; r++) {
            int idx = r * NTHR + l;
            buf[slot(idx >> 3, idx & 7)] = gin_h[idx];
        }
        __syncthreads();

        // ---- Pass 1: compose this thread's 16-step chunk map ----
        Aff M = {1.f, 0.f, 0.f, 1.f, 0.f, 0.f};
#pragma unroll 4
        for (int o = 0; o < F4C; o++) {
            float4 d = buf[slot(l, o)];
            M = compose(step_map(d.x, d.y), M);
            M = compose(step_map(d.z, d.w), M);
        }

        // ---- Pass 2: block-wide scan ----
#pragma unroll
        for (int off = 1; off < 32; off <<= 1) {
            Aff o = shfl_up_aff(M, off);
            if (lane >= off) M = compose(M, o);
        }

        if (lane == 31) wsum[w] = M;
        __syncthreads();

        // prefix over preceding warps + total half map (for the carry)
        Aff pre    = {1.f, 0.f, 0.f, 1.f, 0.f, 0.f};
        Aff preAll = {1.f, 0.f, 0.f, 1.f, 0.f, 0.f};
#pragma unroll
        for (int j = 0; j < NTHR / 32; j++) {
            if (j == w) pre = preAll;
            preAll = compose(wsum[j], preAll);
        }

        Aff eo = shfl_up_aff(M, 1);
        Aff excl;
        if (lane == 0) { excl.a11 = 1.f; excl.a12 = 0.f; excl.a21 = 0.f;
                         excl.a22 = 1.f; excl.b1 = 0.f;  excl.b2 = 0.f; }
        else           { excl = eo; }

        Aff tot = compose(excl, pre);      // exclusive prefix within half

        // state entering this thread's chunk
        float v = fmaf(tot.a11, vh, fmaf(tot.a12, xh, tot.b1));
        float x = fmaf(tot.a21, vh, fmaf(tot.a22, xh, tot.b2));

        // carry: state entering the next half
        float vh2 = fmaf(preAll.a11, vh, fmaf(preAll.a12, xh, preAll.b1));
        float xh2 = fmaf(preAll.a21, vh, fmaf(preAll.a22, xh, preAll.b2));
        vh = vh2; xh = xh2;

        // ---- Pass 3: replay chunk, write xddot in place ----
        // Output float4 j consumes input float4s 2j,2j+1; overwrites slot j
        // (j <= 2j: already consumed). Chunks are thread-private, no hazard.
#pragma unroll 2
        for (int j = 0; j < O4C; j++) {
            float4 d0 = buf[slot(l, 2 * j)];
            float4 d1 = buf[slot(l, 2 * j + 1)];
            float4 o4;
            o4.x = step_state(d0.x, d0.y, v, x);
            o4.y = step_state(d0.z, d0.w, v, x);
            o4.z = step_state(d1.x, d1.y, v, x);
            o4.w = step_state(d1.z, d1.w, v, x);
            buf[slot(l, j)] = o4;
        }
        __syncthreads();

        // ---- Drain: swizzled smem -> coalesced global store ----
#pragma unroll
        for (int r = 0; r < O4C; r++) {
            int idx = r * NTHR + l;
            gout_h[idx] = buf[slot(idx >> 2, idx & 3)];
        }
        __syncthreads();   // buf + wsum reuse in next half
    }
}

extern "C" void kernel_launch(void* const* d_in, const int* in_sizes, int n_in,
                              void* d_out, int out_size) {
    const float* in = (const float*)d_in[0];       // (B, T, 2) float32
    const float* vi = (const float*)d_in[1];       // (B, 1)
    const float* xi = (const float*)d_in[2];       // (B, 1)
    float* out = (float*)d_out;                    // (B, T, 1) float32
    const int B = in_sizes[1];                     // 4096
    spring_scan_kernel<<<B, NTHR>>>(in, vi, xi, out);
}